// round 6
// baseline (speedup 1.0000x reference)
#include <cuda_runtime.h>
#include <cuda_bf16.h>
#include <cstdint>

// Problem constants
#define BS       32
#define SEQ_LEN  4096
#define HIDDEN   1024
#define TPB      128        // 4 independent warps per CTA
#define QSPLIT   (HIDDEN / TPB)   // 8 CTAs per batch row

__device__ __forceinline__ unsigned rotl32(unsigned x, int r) {
    return (x << r) | (x >> (32 - r));
}

// grid = (QSPLIT, BS), block = TPB. No smem, no __syncthreads: every warp
// independently finds the mask prefix via a 2-level probe, then gathers.
__global__ void __launch_bounds__(TPB, 1)
condensed_embracement_kernel(const float* __restrict__ tokens,
                             const int*   __restrict__ mask,
                             float*       __restrict__ out) {
    const int b    = blockIdx.y;
    const int t    = threadIdx.x;
    const int lane = t & 31;
    const int e    = blockIdx.x * TPB + t;          // emb index 0..1023

    // ---- Threefry first (no mask dependence; overlaps probe latency) ----
    // Partitionable threefry-2x32: element j -> lanes (0, j), key (0, 42),
    // bits = out0 ^ out1.
    const unsigned j  = (unsigned)(b * HIDDEN + e);
    const unsigned k0 = 0u;
    const unsigned k1 = 42u;
    const unsigned k2 = k0 ^ k1 ^ 0x1BD11BDAu;

    unsigned x0 = 0u + k0;
    unsigned x1 = j  + k1;

    // ---- Level-1 probe: sample 32 positions at stride 64 over [2048, 4096) ----
    // lengths are guaranteed in [2048, 4096], so [0, 2048) is all ones.
    const int* mrow = mask + (size_t)b * SEQ_LEN;
    const int v1 = __ldg(&mrow[2048 + 64 * lane]);

    #define TF_ROUND(r) { x0 += x1; x1 = rotl32(x1, (r)); x1 ^= x0; }
    TF_ROUND(13) TF_ROUND(15) TF_ROUND(26) TF_ROUND(6)
    x0 += k1; x1 += k2 + 1u;
    TF_ROUND(17) TF_ROUND(29) TF_ROUND(16) TF_ROUND(24)
    x0 += k2; x1 += k0 + 2u;

    const unsigned ones_mask = __ballot_sync(0xffffffffu, v1 != 0);
    const int c = __popc(ones_mask);               // # of one-samples (prefix!)
    const int A = 1984 + 64 * c;                   // first-zero lies in (A, A+64]

    // ---- Level-2 probe: 16 lanes x int4 over aligned block [A, A+64) ----
    int cnt = 0;
    if (lane < 16) {
        int4 w = __ldg(reinterpret_cast<const int4*>(mrow + A) + lane);
        cnt = w.x + w.y + w.z + w.w;               // values are exactly 0/1
    }

    TF_ROUND(13) TF_ROUND(15) TF_ROUND(26) TF_ROUND(6)
    x0 += k0; x1 += k1 + 3u;
    TF_ROUND(17) TF_ROUND(29) TF_ROUND(16) TF_ROUND(24)
    x0 += k1; x1 += k2 + 4u;
    TF_ROUND(13) TF_ROUND(15) TF_ROUND(26) TF_ROUND(6)
    x0 += k2; x1 += k0 + 5u;
    #undef TF_ROUND

    const unsigned bits = x0 ^ x1;
    // uniform in [0,1): bitcast((bits>>9) | 0x3f800000) - 1.0f (JAX-exact)
    const float u = __fsub_rn(__uint_as_float((bits >> 9) | 0x3f800000u), 1.0f);

    // L = A + ones-in-block (covers "zero exactly at A+64" and L=4096 cases)
    const int ones2  = __reduce_add_sync(0xffffffffu, cnt);
    const int prefix = A + ones2;
    const int n_valid = max(prefix - 1, 1);

    // idx = min(int(u * n_valid), n_valid - 1); f32 RN mul, truncating convert
    int idx = (int)__fmul_rn(u, (float)n_valid);
    idx = min(idx, n_valid - 1);

    // ---- Gather (scattered by construction) ----
    out[(size_t)b * HIDDEN + e] =
        __ldcs(&tokens[(size_t)b * SEQ_LEN * HIDDEN + (size_t)idx * HIDDEN + e]);
}

extern "C" void kernel_launch(void* const* d_in, const int* in_sizes, int n_in,
                              void* d_out, int out_size) {
    // Defensive input dispatch by element count (tokens = 32*4096*1024).
    const float* tokens;
    const int*   mask;
    if (in_sizes[0] == BS * SEQ_LEN * HIDDEN) {
        tokens = (const float*)d_in[0];
        mask   = (const int*)d_in[1];
    } else {
        tokens = (const float*)d_in[1];
        mask   = (const int*)d_in[0];
    }
    float* out = (float*)d_out;   // (32, 1024) fp32
    (void)n_in; (void)out_size;

    dim3 grid(QSPLIT, BS);
    condensed_embracement_kernel<<<grid, TPB>>>(tokens, mask, out);
}

// round 7
// speedup vs baseline: 1.0337x; 1.0337x over previous
#include <cuda_runtime.h>
#include <cuda_bf16.h>
#include <cstdint>

// Problem constants
#define BS       32
#define SEQ_LEN  4096
#define HIDDEN   1024
#define TPB      1024
#define NWARP    (TPB / 32)

__device__ __forceinline__ unsigned rotl32(unsigned x, int r) {
    return (x << r) | (x >> (32 - r));
}

// One CTA per batch row, 1024 threads; thread t owns emb index t.
// Lengths are in [2048, 4096], so mask[0:2048) is all ones: only scan the top half.
__global__ void __launch_bounds__(TPB, 1)
condensed_embracement_kernel(const float* __restrict__ tokens,
                             const int*   __restrict__ mask,
                             float*       __restrict__ out) {
    const int b = blockIdx.x;
    const int t = threadIdx.x;

    // ---- Phase 1 load: 2048 ints over [2048,4096), one int2 per thread ----
    const int2* m2 =
        reinterpret_cast<const int2*>(mask + (size_t)b * SEQ_LEN + 2048);
    const int2 mv = __ldg(&m2[t]);

    // ---- Threefry (mask-independent; fills the load shadow) ----
    // Partitionable threefry-2x32: element j -> lanes (0, j), key (0, 42),
    // bits = out0 ^ out1.
    const unsigned j  = (unsigned)(b * HIDDEN + t);
    const unsigned k0 = 0u;
    const unsigned k1 = 42u;
    const unsigned k2 = k0 ^ k1 ^ 0x1BD11BDAu;

    unsigned x0 = 0u + k0;
    unsigned x1 = j  + k1;

    #define TF_ROUND(r) { x0 += x1; x1 = rotl32(x1, (r)); x1 ^= x0; }
    TF_ROUND(13) TF_ROUND(15) TF_ROUND(26) TF_ROUND(6)
    x0 += k1; x1 += k2 + 1u;
    TF_ROUND(17) TF_ROUND(29) TF_ROUND(16) TF_ROUND(24)
    x0 += k2; x1 += k0 + 2u;
    TF_ROUND(13) TF_ROUND(15) TF_ROUND(26) TF_ROUND(6)
    x0 += k0; x1 += k1 + 3u;
    TF_ROUND(17) TF_ROUND(29) TF_ROUND(16) TF_ROUND(24)
    x0 += k1; x1 += k2 + 4u;
    TF_ROUND(13) TF_ROUND(15) TF_ROUND(26) TF_ROUND(6)
    x0 += k2; x1 += k0 + 5u;
    #undef TF_ROUND

    const unsigned bits = x0 ^ x1;
    // uniform in [0,1): bitcast((bits>>9) | 0x3f800000) - 1.0f (JAX-exact)
    const float u = __fsub_rn(__uint_as_float((bits >> 9) | 0x3f800000u), 1.0f);

    // ---- Phase 1 reduce: prefix = 2048 + sum(top half) ----
    int s = mv.x + mv.y;
    s = __reduce_add_sync(0xffffffffu, s);          // REDUX.SUM per warp

    __shared__ int wsum[NWARP];
    __shared__ int prefix_sh;
    if ((t & 31) == 0) wsum[t >> 5] = s;
    __syncthreads();
    if (t < 32) {
        int x = __reduce_add_sync(0xffffffffu, wsum[t]);
        if (t == 0) prefix_sh = x;
    }
    __syncthreads();

    const int prefix  = 2048 + prefix_sh;
    const int n_valid = max(prefix - 1, 1);

    // idx = min(int(u * n_valid), n_valid - 1); f32 RN mul, truncating convert
    int idx = (int)__fmul_rn(u, (float)n_valid);
    idx = min(idx, n_valid - 1);

    // ---- Phase 2: gather (scattered by construction) ----
    out[(size_t)b * HIDDEN + t] =
        tokens[(size_t)b * SEQ_LEN * HIDDEN + (size_t)idx * HIDDEN + t];
}

extern "C" void kernel_launch(void* const* d_in, const int* in_sizes, int n_in,
                              void* d_out, int out_size) {
    // Defensive input dispatch by element count (tokens = 32*4096*1024).
    const float* tokens;
    const int*   mask;
    if (in_sizes[0] == BS * SEQ_LEN * HIDDEN) {
        tokens = (const float*)d_in[0];
        mask   = (const int*)d_in[1];
    } else {
        tokens = (const float*)d_in[1];
        mask   = (const int*)d_in[0];
    }
    float* out = (float*)d_out;   // (32, 1024) fp32
    (void)n_in; (void)out_size;

    condensed_embracement_kernel<<<BS, TPB>>>(tokens, mask, out);
}

// round 9
// speedup vs baseline: 1.0437x; 1.0097x over previous
#include <cuda_runtime.h>
#include <cuda_bf16.h>
#include <cstdint>

// Problem constants
#define BS       32
#define SEQ_LEN  4096
#define HIDDEN   1024
#define TPB      256
#define VPT      (HIDDEN / TPB)    // outputs per thread = 4
#define NWARP    (TPB / 32)

__device__ __forceinline__ unsigned rotl32(unsigned x, int r) {
    return (x << r) | (x >> (32 - r));
}

__device__ __forceinline__ unsigned threefry_bits(unsigned j) {
    const unsigned k0 = 0u;
    const unsigned k1 = 42u;
    const unsigned k2 = k0 ^ k1 ^ 0x1BD11BDAu;
    unsigned x0 = 0u + k0;
    unsigned x1 = j  + k1;
    #define TF_ROUND(r) { x0 += x1; x1 = rotl32(x1, (r)); x1 ^= x0; }
    TF_ROUND(13) TF_ROUND(15) TF_ROUND(26) TF_ROUND(6)
    x0 += k1; x1 += k2 + 1u;
    TF_ROUND(17) TF_ROUND(29) TF_ROUND(16) TF_ROUND(24)
    x0 += k2; x1 += k0 + 2u;
    TF_ROUND(13) TF_ROUND(15) TF_ROUND(26) TF_ROUND(6)
    x0 += k0; x1 += k1 + 3u;
    TF_ROUND(17) TF_ROUND(29) TF_ROUND(16) TF_ROUND(24)
    x0 += k1; x1 += k2 + 4u;
    TF_ROUND(13) TF_ROUND(15) TF_ROUND(26) TF_ROUND(6)
    x0 += k2; x1 += k0 + 5u;
    #undef TF_ROUND
    return x0 ^ x1;
}

// One CTA per batch row; 256 threads; thread t owns emb {t, t+256, t+512, t+768}.
// Lengths are in [2048, 4096] -> mask[0:2048) is all ones; scan only the top half.
__global__ void __launch_bounds__(TPB, 1)
condensed_embracement_kernel(const float* __restrict__ tokens,
                             const int*   __restrict__ mask,
                             float*       __restrict__ out) {
    const int b = blockIdx.x;
    const int t = threadIdx.x;

    // ---- Phase 1 load: 2048 ints over [2048,4096), two int4 per thread ----
    const int4* m4 =
        reinterpret_cast<const int4*>(mask + (size_t)b * SEQ_LEN + 2048);
    const int4 a0 = __ldg(&m4[t]);
    const int4 a1 = __ldg(&m4[t + TPB]);

    // ---- 4 independent threefries (fill the load shadow, full ILP) ----
    unsigned bits[VPT];
    #pragma unroll
    for (int k = 0; k < VPT; k++)
        bits[k] = threefry_bits((unsigned)(b * HIDDEN + k * TPB + t));

    // ---- Phase 1 reduce: prefix = 2048 + sum(top half) ----
    int s = a0.x + a0.y + a0.z + a0.w + a1.x + a1.y + a1.z + a1.w;
    s = __reduce_add_sync(0xffffffffu, s);          // REDUX.SUM per warp

    __shared__ int wsum[NWARP];
    if ((t & 31) == 0) wsum[t >> 5] = s;
    __syncthreads();
    int prefix = 2048;
    #pragma unroll
    for (int w = 0; w < NWARP; w++) prefix += wsum[w];

    const int n_valid = max(prefix - 1, 1);
    const float nvf   = (float)n_valid;

    // ---- Phase 2: 4 independent gathers (MLP=4) ----
    const float* trow = tokens + (size_t)b * SEQ_LEN * HIDDEN;
    float* orow = out + (size_t)b * HIDDEN;
    #pragma unroll
    for (int k = 0; k < VPT; k++) {
        const int e = k * TPB + t;
        // uniform in [0,1): bitcast((bits>>9)|0x3f800000) - 1.0f (JAX-exact)
        const float u = __fsub_rn(
            __uint_as_float((bits[k] >> 9) | 0x3f800000u), 1.0f);
        int idx = (int)__fmul_rn(u, nvf);
        idx = min(idx, n_valid - 1);
        orow[e] = trow[(size_t)idx * HIDDEN + e];
    }
}

extern "C" void kernel_launch(void* const* d_in, const int* in_sizes, int n_in,
                              void* d_out, int out_size) {
    // Defensive input dispatch by element count (tokens = 32*4096*1024).
    const float* tokens;
    const int*   mask;
    if (in_sizes[0] == BS * SEQ_LEN * HIDDEN) {
        tokens = (const float*)d_in[0];
        mask   = (const int*)d_in[1];
    } else {
        tokens = (const float*)d_in[1];
        mask   = (const int*)d_in[0];
    }
    float* out = (float*)d_out;   // (32, 1024) fp32
    (void)n_in; (void)out_size;

    condensed_embracement_kernel<<<BS, TPB>>>(tokens, mask, out);
}